// round 1
// baseline (speedup 1.0000x reference)
#include <cuda_runtime.h>
#include <cuda_bf16.h>
#include <math.h>

#define NN 50000
#define EE 800000
#define NG 512
#define C1 128
#define C2 64
#define EPS 1e-5f

// ---------------- scratch (static device memory; no allocation) ----------------
__device__ float  g_deg[NN];
__device__ float  g_dinv[NN];
__device__ float  g_y4[NN * 4];
__device__ float  g_h1[(size_t)NN * C1];
__device__ float  g_z2[(size_t)NN * C2];   // conv2 pre-agg; later overwritten with h2relu
__device__ float  g_a2[(size_t)NN * C2];   // edge aggregation target
__device__ double g_bnsum1[C1], g_bnsq1[C1];
__device__ double g_bnsum2[C2], g_bnsq2[C2];
__device__ float  g_a1c[C1], g_c1c[C1];
__device__ float  g_a2c[C2], g_c2c[C2];
__device__ float  g_a3c[C2], g_c3c[C2];
__device__ float  g_hg[NG * C2];
__device__ float  g_hg1[NG * C2];
__device__ int    g_is64;

// ---------------- helpers ----------------
__device__ __forceinline__ void redAdd4(float* addr, float4 v) {
    asm volatile("red.global.add.v4.f32 [%0], {%1,%2,%3,%4};"
                 :: "l"(__cvta_generic_to_global(addr)),
                    "f"(v.x), "f"(v.y), "f"(v.z), "f"(v.w)
                 : "memory");
}

__device__ __forceinline__ int edgeIdx(const void* p, long i, int is64) {
    return is64 ? (int)((const long long*)p)[i] : ((const int*)p)[i];
}

// ---------------- kernels ----------------
__global__ void kDetect(const void* ei) {
    if (threadIdx.x == 0 && blockIdx.x == 0) {
        const long long* p = (const long long*)ei;
        int ok = 1;
        for (int i = 0; i < 16; i++) {
            long long v = p[i];
            if (v < 0 || v >= NN) ok = 0;
        }
        g_is64 = ok;
    }
}

__global__ void kDeg(const void* ei) {
    int e = blockIdx.x * blockDim.x + threadIdx.x;
    if (e < EE) {
        int d = edgeIdx(ei, (long)EE + e, g_is64);
        atomicAdd(&g_deg[d], 1.0f);
    }
}

__global__ void kDinv() {
    int i = blockIdx.x * blockDim.x + threadIdx.x;
    if (i < NN) g_dinv[i] = rsqrtf(g_deg[i] + 1.0f);
}

// layer-1 aggregation in input space (4 floats/edge)
__global__ void kY4(const void* ei, const float* x) {
    int e = blockIdx.x * blockDim.x + threadIdx.x;
    if (e < EE) {
        int is64 = g_is64;
        int s = edgeIdx(ei, e, is64);
        int d = edgeIdx(ei, (long)EE + e, is64);
        float di = g_dinv[s];
        float4 xv = ((const float4*)x)[s];
        xv.x *= di; xv.y *= di; xv.z *= di; xv.w *= di;
        redAdd4(&g_y4[d * 4], xv);
    }
}

// conv1: h1 = relu(dinv*((y4 + dinv*x) @ W1) + b1); accumulate BN1 stats
__global__ void kConv1(const float* x, const float* W1, const float* b1) {
    int t = threadIdx.x;  // channel 0..127
    float w0 = W1[t], w1 = W1[C1 + t], w2 = W1[2 * C1 + t], w3 = W1[3 * C1 + t];
    float bb = b1[t];
    float s = 0.f, sq = 0.f;
    for (int i = blockIdx.x; i < NN; i += gridDim.x) {
        float di = g_dinv[i];
        float4 yv = *(const float4*)&g_y4[i * 4];
        float4 xv = ((const float4*)x)[i];
        float y0 = yv.x + di * xv.x;
        float y1 = yv.y + di * xv.y;
        float y2 = yv.z + di * xv.z;
        float y3 = yv.w + di * xv.w;
        float h = di * (y0 * w0 + y1 * w1 + y2 * w2 + y3 * w3) + bb;
        h = fmaxf(h, 0.f);
        g_h1[(size_t)i * C1 + t] = h;
        s += h; sq += h * h;
    }
    atomicAdd(&g_bnsum1[t], (double)s);
    atomicAdd(&g_bnsq1[t], (double)sq);
}

__global__ void kBN1(const float* g1, const float* be1) {
    int t = threadIdx.x;
    if (t < C1) {
        double m = g_bnsum1[t] / NN;
        double v = g_bnsq1[t] / NN - m * m;
        float a = g1[t] * rsqrtf((float)v + EPS);
        g_a1c[t] = a;
        g_c1c[t] = be1[t] - (float)m * a;
    }
}

// z2 = BN1(h1) @ W2, 4 nodes per block iteration, W2 staged in shared
__global__ void kZ2(const float* W2) {
    __shared__ float Ws[C1 * C2];
    __shared__ float Hs[4][C1];
    __shared__ float a1s[C1], c1s[C1];
    int tid = threadIdx.x;  // 256
    for (int i = tid; i < C1 * C2; i += 256) Ws[i] = W2[i];
    if (tid < C1) { a1s[tid] = g_a1c[tid]; c1s[tid] = g_c1c[tid]; }
    __syncthreads();
    int sub = tid >> 6;      // node slot 0..3
    int j = tid & 63;        // output channel
    const long NGRP = (NN + 3) / 4;
    for (long grp = blockIdx.x; grp < NGRP; grp += gridDim.x) {
        long n0 = grp * 4;
        for (int v = tid; v < 4 * C1; v += 256) {
            int nn = v >> 7, k = v & 127;
            long node = n0 + nn;
            float h = (node < NN) ? g_h1[node * C1 + k] : 0.f;
            Hs[nn][k] = h * a1s[k] + c1s[k];
        }
        __syncthreads();
        long node = n0 + sub;
        if (node < NN) {
            float acc = 0.f;
            #pragma unroll 16
            for (int k = 0; k < C1; k++) acc += Hs[sub][k] * Ws[k * C2 + j];
            g_z2[node * C2 + j] = acc;
        }
        __syncthreads();
    }
}

// layer-2 edge aggregation: a2[dst] += dinv[src] * z2[src]  (16 threads/edge, float4 each)
__global__ void kAgg2(const void* ei) {
    long gid = (long)blockIdx.x * blockDim.x + threadIdx.x;
    long e = gid >> 4;
    int lane = (int)(gid & 15);
    if (e < EE) {
        int is64 = g_is64;
        int s = edgeIdx(ei, e, is64);
        int d = edgeIdx(ei, (long)EE + e, is64);
        float di = g_dinv[s];
        float4 v = *(const float4*)&g_z2[(size_t)s * C2 + lane * 4];
        v.x *= di; v.y *= di; v.z *= di; v.w *= di;
        redAdd4(&g_a2[(size_t)d * C2 + lane * 4], v);
    }
}

// conv2 finish: h2 = relu(dinv*(a2 + dinv*z2) + b2); overwrite z2; BN2 stats
__global__ void kConv2(const float* b2) {
    int t = threadIdx.x;  // 0..63
    float bb = b2[t];
    float s = 0.f, sq = 0.f;
    for (int i = blockIdx.x; i < NN; i += gridDim.x) {
        float di = g_dinv[i];
        size_t off = (size_t)i * C2 + t;
        float z = g_z2[off];
        float a = g_a2[off];
        float h = di * (a + di * z) + bb;
        h = fmaxf(h, 0.f);
        g_z2[off] = h;
        s += h; sq += h * h;
    }
    atomicAdd(&g_bnsum2[t], (double)s);
    atomicAdd(&g_bnsq2[t], (double)sq);
}

__global__ void kBN2(const float* g2, const float* be2) {
    int t = threadIdx.x;
    if (t < C2) {
        double m = g_bnsum2[t] / NN;
        double v = g_bnsq2[t] / NN - m * m;
        float a = g2[t] * rsqrtf((float)v + EPS);
        g_a2c[t] = a;
        g_c2c[t] = be2[t] - (float)m * a;
    }
}

// global_add_pool of BN2(h2) into hg[batch]
__global__ void kPool(const void* batch) {
    long gid = (long)blockIdx.x * blockDim.x + threadIdx.x;
    long i = gid >> 4;
    int lane = (int)(gid & 15);
    if (i < NN) {
        int b = g_is64 ? (int)((const long long*)batch)[i] : ((const int*)batch)[i];
        float4 v = *(const float4*)&g_z2[(size_t)i * C2 + lane * 4];
        int c = lane * 4;
        v.x = v.x * g_a2c[c]     + g_c2c[c];
        v.y = v.y * g_a2c[c + 1] + g_c2c[c + 1];
        v.z = v.z * g_a2c[c + 2] + g_c2c[c + 2];
        v.w = v.w * g_a2c[c + 3] + g_c2c[c + 3];
        redAdd4(&g_hg[b * C2 + c], v);
    }
}

__global__ void kFc1(const float* fW1, const float* fb1) {
    __shared__ float hs[C2];
    int g = blockIdx.x, j = threadIdx.x;
    hs[j] = g_hg[g * C2 + j];
    __syncthreads();
    float acc = fb1[j];
    #pragma unroll 8
    for (int k = 0; k < C2; k++) acc += hs[k] * fW1[k * C2 + j];
    g_hg1[g * C2 + j] = fmaxf(acc, 0.f);
}

__global__ void kBN3(const float* g3, const float* be3) {
    int j = threadIdx.x;  // 0..63
    float s = 0.f, sq = 0.f;
    for (int g = 0; g < NG; g++) {
        float v = g_hg1[g * C2 + j];
        s += v; sq += v * v;
    }
    float m = s / NG;
    float var = sq / NG - m * m;
    float a = g3[j] * rsqrtf(var + EPS);
    g_a3c[j] = a;
    g_c3c[j] = be3[j] - m * a;
}

__global__ void kOut(const float* fW2, const float* fb2,
                     const float* fW3, const float* fb3, float* out) {
    __shared__ float hs[C2], ts[C2], os[3];
    int g = blockIdx.x, j = threadIdx.x;
    hs[j] = g_hg1[g * C2 + j] * g_a3c[j] + g_c3c[j];
    __syncthreads();
    float acc = fb2[j];
    #pragma unroll 8
    for (int k = 0; k < C2; k++) acc += hs[k] * fW2[k * C2 + j];
    ts[j] = fmaxf(acc, 0.f);
    __syncthreads();
    if (j < 3) {
        float o = fb3[j];
        for (int k = 0; k < C2; k++) o += ts[k] * fW3[k * 3 + j];
        os[j] = o;
    }
    __syncthreads();
    if (j == 0) {
        float mx = fmaxf(os[0], fmaxf(os[1], os[2]));
        float lse = mx + logf(expf(os[0] - mx) + expf(os[1] - mx) + expf(os[2] - mx));
        out[g * 3 + 0] = os[0] - lse;
        out[g * 3 + 1] = os[1] - lse;
        out[g * 3 + 2] = os[2] - lse;
    }
}

// ---------------- host ----------------
extern "C" void kernel_launch(void* const* d_in, const int* in_sizes, int n_in,
                              void* d_out, int out_size) {
    const float* x   = (const float*)d_in[0];
    const void*  ei  = d_in[1];
    const void*  bat = d_in[2];
    const float* W1  = (const float*)d_in[3];
    const float* b1  = (const float*)d_in[4];
    const float* g1  = (const float*)d_in[5];
    const float* be1 = (const float*)d_in[6];
    const float* W2  = (const float*)d_in[7];
    const float* b2  = (const float*)d_in[8];
    const float* g2  = (const float*)d_in[9];
    const float* be2 = (const float*)d_in[10];
    const float* fW1 = (const float*)d_in[11];
    const float* fb1 = (const float*)d_in[12];
    const float* g3  = (const float*)d_in[13];
    const float* be3 = (const float*)d_in[14];
    const float* fW2 = (const float*)d_in[15];
    const float* fb2 = (const float*)d_in[16];
    const float* fW3 = (const float*)d_in[17];
    const float* fb3 = (const float*)d_in[18];
    float* out = (float*)d_out;

    void *p_deg, *p_y4, *p_a2, *p_hg, *p_s1, *p_q1, *p_s2, *p_q2;
    cudaGetSymbolAddress(&p_deg, g_deg);
    cudaGetSymbolAddress(&p_y4,  g_y4);
    cudaGetSymbolAddress(&p_a2,  g_a2);
    cudaGetSymbolAddress(&p_hg,  g_hg);
    cudaGetSymbolAddress(&p_s1,  g_bnsum1);
    cudaGetSymbolAddress(&p_q1,  g_bnsq1);
    cudaGetSymbolAddress(&p_s2,  g_bnsum2);
    cudaGetSymbolAddress(&p_q2,  g_bnsq2);

    cudaMemsetAsync(p_deg, 0, NN * sizeof(float));
    cudaMemsetAsync(p_y4,  0, NN * 4 * sizeof(float));
    cudaMemsetAsync(p_a2,  0, (size_t)NN * C2 * sizeof(float));
    cudaMemsetAsync(p_hg,  0, NG * C2 * sizeof(float));
    cudaMemsetAsync(p_s1,  0, C1 * sizeof(double));
    cudaMemsetAsync(p_q1,  0, C1 * sizeof(double));
    cudaMemsetAsync(p_s2,  0, C2 * sizeof(double));
    cudaMemsetAsync(p_q2,  0, C2 * sizeof(double));

    kDetect<<<1, 32>>>(ei);
    kDeg<<<(EE + 255) / 256, 256>>>(ei);
    kDinv<<<(NN + 255) / 256, 256>>>();
    kY4<<<(EE + 255) / 256, 256>>>(ei, x);
    kConv1<<<512, 128>>>(x, W1, b1);
    kBN1<<<1, 128>>>(g1, be1);
    kZ2<<<888, 256>>>(W2);
    {
        long total = (long)EE * 16;
        kAgg2<<<(unsigned)((total + 255) / 256), 256>>>(ei);
    }
    kConv2<<<512, 64>>>(b2);
    kBN2<<<1, 64>>>(g2, be2);
    {
        long total = (long)NN * 16;
        kPool<<<(unsigned)((total + 255) / 256), 256>>>(bat);
    }
    kFc1<<<NG, 64>>>(fW1, fb1);
    kBN3<<<1, 64>>>(g3, be3);
    kOut<<<NG, 64>>>(fW2, fb2, fW3, fb3, out);
}